// round 12
// baseline (speedup 1.0000x reference)
#include <cuda_runtime.h>
#include <cuda_bf16.h>
#include <cstdint>

#define N_ROWS 131072
#define DIM 128
#define KCB 1024
#define BM 128
#define PRECF 1e7f
#define NCAND 16
#define MARGIN 6e-2f
#define FIXMARGIN 4.5e-2f

// padded row: 128 bf16 = 256B + 16B pad = 272B (conflict-free ldmatrix)
#define ROWB 272
#define TILEB (BM * ROWB)          // 34816 bytes: one 128x128 bf16 tile

// smem layout (109056 total -> 2 CTAs/SM)
#define SM_XH  0
#define SM_E   TILEB                       // + buf*TILEB, 2 buffers
#define SM_ESQ (3 * TILEB)                 // 1024 floats
#define SM_CNT (SM_ESQ + 4096)             // 128 ints
#define SMEM_BYTES (SM_CNT + 512)          // 109056

// ---- device scratch ----
__device__ int     g_ind[N_ROWS];
__device__ float   g_esq[KCB];
__device__ float   g_Eq[KCB * DIM];          // qt(E), natural layout (fix path)
__device__ uint8_t g_Ehi[8 * TILEB];         // per chunk: bf16-hi tile, padded
__device__ int2    g_cand[(size_t)N_ROWS * NCAND];
__device__ int     g_ncand[N_ROWS];
__device__ int     g_work[N_ROWS];
__device__ int     g_nwork;
__device__ int     g_cnti[KCB];
__device__ int     g_off[KCB];
__device__ int     g_slot[N_ROWS];
__device__ int     g_rowlist[N_ROWS];
__device__ float   g_smoothed[KCB];

__device__ __forceinline__ float qt(float t) {
    return __fdiv_rn(rintf(__fmul_rn(t, PRECF)), PRECF);
}
__device__ __forceinline__ uint32_t smem_u32(const void* p) {
    return (uint32_t)__cvta_generic_to_shared(p);
}
__device__ __forceinline__ void cp16(uint32_t dst, const void* src) {
    asm volatile("cp.async.cg.shared.global [%0], [%1], 16;" :: "r"(dst), "l"(src));
}
__device__ __forceinline__ void cp_commit() { asm volatile("cp.async.commit_group;"); }
template <int N>
__device__ __forceinline__ void cp_wait() {
    asm volatile("cp.async.wait_group %0;" :: "n"(N));
}
__device__ __forceinline__ void ldsm4(uint32_t* r, uint32_t addr) {
    asm volatile("ldmatrix.sync.aligned.m8n8.x4.shared.b16 {%0,%1,%2,%3},[%4];"
                 : "=r"(r[0]), "=r"(r[1]), "=r"(r[2]), "=r"(r[3]) : "r"(addr));
}
__device__ __forceinline__ void mma_bf16(float* d, const uint32_t* a,
                                         uint32_t b0, uint32_t b1) {
    asm volatile(
        "mma.sync.aligned.m16n8k16.row.col.f32.bf16.bf16.f32 "
        "{%0,%1,%2,%3},{%4,%5,%6,%7},{%8,%9},{%0,%1,%2,%3};"
        : "+f"(d[0]), "+f"(d[1]), "+f"(d[2]), "+f"(d[3])
        : "r"(a[0]), "r"(a[1]), "r"(a[2]), "r"(a[3]), "r"(b0), "r"(b1));
}

// exact R4 GPU-shape x_sq over one 128-float row
__device__ float xsq_row(const float* __restrict__ v) {
    float s[32];
    #pragma unroll
    for (int t = 0; t < 32; t++) {
        float a0 = v[2 * t], a1 = v[2 * t + 1];
        float b0 = v[64 + 2 * t], b1 = v[64 + 2 * t + 1];
        float p0 = __fmaf_rn(b0, b0, __fmaf_rn(a0, a0, 0.0f));
        float p1 = __fmaf_rn(b1, b1, __fmaf_rn(a1, a1, 0.0f));
        s[t] = __fadd_rn(p0, p1);
    }
    #pragma unroll
    for (int off = 16; off; off >>= 1)
        #pragma unroll
        for (int t = 0; t < off; t++)
            s[t] = __fadd_rn(s[t], s[t + off]);
    return qt(s[0]);
}

// exact dist for one (row, code): bit-identical to the R4 chain
__device__ __forceinline__ float exact_dist(const float* __restrict__ xr,
                                            float xsq, int c) {
    const float* e = g_Eq + (size_t)c * DIM;
    float dot = 0.0f;
    #pragma unroll 8
    for (int d = 0; d < DIM; d++)
        dot = __fmaf_rn(xr[d], e[d], dot);
    float c3 = qt(__fmul_rn(qt(dot), 2.0f));
    float S  = qt(__fadd_rn(xsq, g_esq[c]));
    return -qt(__fsub_rn(S, c3));
}

// ---------------------------------------------------------------------------
// k_pre: qt(E); bf16-hi into padded chunk tiles; zero counters
// ---------------------------------------------------------------------------
__global__ void k_pre(const float* __restrict__ embed) {
    int k = blockIdx.x;
    int d = threadIdx.x;
    float eq = qt(embed[k * DIM + d]);
    g_Eq[k * DIM + d] = eq;
    *(__nv_bfloat16*)(g_Ehi + (size_t)(k >> 7) * TILEB + (k & 127) * ROWB + d * 2) =
        __float2bfloat16(eq);
    if (d == 0) {
        g_cnti[k] = 0;
        if (k == 0) g_nwork = 0;
    }
}

// ---------------------------------------------------------------------------
// k_esq: XLA:GPU column-reduction emulation (bit-exact, proven R4)
// ---------------------------------------------------------------------------
__global__ void k_esq(const float* __restrict__ embed) {
    int k = blockIdx.x * 128 + threadIdx.x;
    const float* row = embed + (size_t)k * DIM;
    float s[32];
    #pragma unroll
    for (int j = 0; j < 32; j++) {
        float p = 0.0f;
        #pragma unroll
        for (int i = 0; i < 4; i++) {
            float e = qt(row[j + 32 * i]);
            p = __fmaf_rn(e, e, p);
        }
        s[j] = p;
    }
    #pragma unroll
    for (int off = 16; off; off >>= 1)
        #pragma unroll
        for (int t = 0; t < off; t++)
            s[t] = __fadd_rn(s[t], s[t + off]);
    g_esq[k] = qt(s[0]);
}

// ---------------------------------------------------------------------------
// k_main: HMMA bf16 1-term screen. Warp tile 32 rows x 64 codes:
// warp w: rows (w&3)*32..+32, codes (w>>2)*64..+64 of each chunk.
// B smem traffic halved vs 16x128 tiling (the R11 bottleneck).
// ---------------------------------------------------------------------------
__global__ __launch_bounds__(256, 2)
void k_main(const float* __restrict__ x) {
    extern __shared__ char smem[];
    uint32_t sb = smem_u32(smem);
    float* esq_s = (float*)(smem + SM_ESQ);
    int*   cnt_s = (int*)(smem + SM_CNT);

    int tid = threadIdx.x;
    int warp = tid >> 5;
    int lane = tid & 31;
    int g = lane >> 2, tig = lane & 3;
    int mg = warp & 3;            // row group: rows mg*32..+32
    int cg = warp >> 2;           // code group: codes cg*64..+64 per chunk
    int rb = mg * 32;
    int row0 = blockIdx.x * BM;

    if (tid < BM) cnt_s[tid] = 0;

    // prefetch E chunks 0 and 1
    #pragma unroll
    for (int b = 0; b < 2; b++) {
        #pragma unroll
        for (int s = 0; s < 9; s++) {
            int gr = tid + s * 256;
            if (gr < TILEB / 16)
                cp16(sb + SM_E + b * TILEB + gr * 16,
                     g_Ehi + (size_t)b * TILEB + gr * 16);
        }
        cp_commit();
    }

    // X load -> bf16 hi tile
    #pragma unroll
    for (int s = 0; s < 32; s++) {
        int p = tid + s * 256;                 // 8192 pairs
        int row = p >> 6, d = (p & 63) * 2;
        float2 v = *(const float2*)(x + (size_t)(row0 + row) * DIM + d);
        *(__nv_bfloat162*)(smem + SM_XH + row * ROWB + d * 2) =
            __nv_bfloat162(__float2bfloat16(v.x), __float2bfloat16(v.y));
    }
    #pragma unroll
    for (int s = 0; s < 4; s++) esq_s[tid + s * 256] = g_esq[tid + s * 256];
    __syncthreads();

    // A fragments: 2 m-tiles (rows rb.. and rb+16..) x 8 ksteps, resident
    uint32_t ah[8][8];
    {
        uint32_t a0 = sb + SM_XH + (rb + (lane & 15)) * ROWB + (lane >> 4) * 16;
        uint32_t a1 = a0 + 16 * ROWB;
        #pragma unroll
        for (int s = 0; s < 8; s++) {
            ldsm4(&ah[s][0], a0 + s * 32);
            ldsm4(&ah[s][4], a1 + s * 32);
        }
    }

    // per-thread rows: i -> rb + (i>>1)*16 + (i&1)*8 + g
    float best[4];
    #pragma unroll
    for (int i = 0; i < 4; i++) best[i] = -3.4e38f;

    for (int kc = 0; kc < 8; kc++) {
        if (kc < 7) cp_wait<1>(); else cp_wait<0>();
        __syncthreads();
        uint32_t eb = sb + SM_E + (kc & 1) * TILEB;
        uint32_t bbase = eb + (uint32_t)((cg * 64 + (lane & 7)
                           + ((lane >> 4) << 3)) * ROWB)
                       + (((lane >> 3) & 1) << 4);

        #pragma unroll
        for (int p = 0; p < 4; p++) {          // 16 codes per pass
            float acc[4][4];                   // [mt*2+nt][4]
            #pragma unroll
            for (int f = 0; f < 4; f++)
                #pragma unroll
                for (int j = 0; j < 4; j++) acc[f][j] = 0.0f;

            uint32_t bp = bbase + (uint32_t)(p * 16 * ROWB);
            #pragma unroll
            for (int s = 0; s < 8; s++) {
                uint32_t b[4];
                ldsm4(b, bp + s * 32);
                mma_bf16(acc[0], &ah[s][0], b[0], b[1]);   // mt0 nt0
                mma_bf16(acc[1], &ah[s][0], b[2], b[3]);   // mt0 nt1
                mma_bf16(acc[2], &ah[s][4], b[0], b[1]);   // mt1 nt0
                mma_bf16(acc[3], &ah[s][4], b[2], b[3]);   // mt1 nt1
            }

            // scores + per-row local maxes
            int cb = kc * 128 + cg * 64 + p * 16 + tig * 2;
            float mloc[4];
            #pragma unroll
            for (int i = 0; i < 4; i++) mloc[i] = -3.4e38f;
            #pragma unroll
            for (int f = 0; f < 4; f++) {
                int mt = f >> 1, nt = f & 1;
                int c = cb + nt * 8;
                float e0 = esq_s[c], e1 = esq_s[c + 1];
                acc[f][0] = __fmaf_rn(2.0f, acc[f][0], -e0);
                acc[f][1] = __fmaf_rn(2.0f, acc[f][1], -e1);
                acc[f][2] = __fmaf_rn(2.0f, acc[f][2], -e0);
                acc[f][3] = __fmaf_rn(2.0f, acc[f][3], -e1);
                mloc[mt * 2]     = fmaxf(mloc[mt * 2],
                                         fmaxf(acc[f][0], acc[f][1]));
                mloc[mt * 2 + 1] = fmaxf(mloc[mt * 2 + 1],
                                         fmaxf(acc[f][2], acc[f][3]));
            }

            // quad reduce per row, update running best/thresholds, push
            #pragma unroll
            for (int i = 0; i < 4; i++) {
                float m = mloc[i];
                m = fmaxf(m, __shfl_xor_sync(0xffffffffu, m, 1));
                m = fmaxf(m, __shfl_xor_sync(0xffffffffu, m, 2));
                best[i] = fmaxf(best[i], m);
            }
            #pragma unroll
            for (int i = 0; i < 4; i++) {
                float thr = best[i] - MARGIN;
                if (mloc[i] >= thr) {
                    int mt = i >> 1, hi = i & 1;
                    int r = rb + mt * 16 + hi * 8 + g;
                    #pragma unroll
                    for (int nt = 0; nt < 2; nt++) {
                        #pragma unroll
                        for (int jj = 0; jj < 2; jj++) {
                            float sc = acc[mt * 2 + nt][hi * 2 + jj];
                            if (sc >= thr) {
                                int slot = atomicAdd(&cnt_s[r], 1);
                                if (slot < NCAND)
                                    g_cand[(size_t)(row0 + r) * NCAND + slot] =
                                        make_int2(__float_as_int(sc),
                                                  cb + nt * 8 + jj);
                            }
                        }
                    }
                }
            }
        }

        __syncthreads();
        if (kc + 2 < 8) {
            #pragma unroll
            for (int s = 0; s < 9; s++) {
                int gr = tid + s * 256;
                if (gr < TILEB / 16)
                    cp16(sb + SM_E + (kc & 1) * TILEB + gr * 16,
                         g_Ehi + (size_t)(kc + 2) * TILEB + gr * 16);
            }
            cp_commit();
        }
    }

    __syncthreads();
    if (tid < BM) g_ncand[row0 + tid] = cnt_s[tid];
}

// ---------------------------------------------------------------------------
// k_fix1: resolve single-qualifier rows (also assigns bucket slot + out_ind);
// push the rest to the worklist
// ---------------------------------------------------------------------------
__global__ void k_fix1(float* __restrict__ out_ind) {
    int row = blockIdx.x * 256 + threadIdx.x;
    int n = g_ncand[row];
    if (n <= NCAND) {
        const int2* cand = &g_cand[(size_t)row * NCAND];
        float mr = -3.4e38f;
        for (int s = 0; s < n; s++)
            mr = fmaxf(mr, __int_as_float(cand[s].x));
        float thr = mr - FIXMARGIN;
        int nq = 0, only = 0;
        for (int s = 0; s < n; s++)
            if (__int_as_float(cand[s].x) >= thr) { nq++; only = cand[s].y; }
        if (nq <= 1) {
            g_ind[row] = only;
            g_slot[row] = atomicAdd(&g_cnti[only], 1);
            out_ind[row] = (float)only;
            return;
        }
    }
    int w = atomicAdd(&g_nwork, 1);
    g_work[w] = row;
}

// ---------------------------------------------------------------------------
// k_fix2: warp per work-row; lane per candidate, bit-exact R4 chain
// ---------------------------------------------------------------------------
__global__ __launch_bounds__(256)
void k_fix2(const float* __restrict__ x, float* __restrict__ out_ind) {
    int gw = (blockIdx.x * 256 + threadIdx.x) >> 5;
    int lane = threadIdx.x & 31;
    int nwarps = gridDim.x * 8;
    int nwork = g_nwork;

    for (int i = gw; i < nwork; i += nwarps) {
        int row = g_work[i];
        const float* xr = x + (size_t)row * DIM;
        int n = g_ncand[row];
        float xsq = xsq_row(xr);

        float bd = -3.4e38f;
        int bi = 0x7FFFFFFF;
        if (n <= NCAND) {
            int2 cd = (lane < n) ? g_cand[(size_t)row * NCAND + lane]
                                 : make_int2((int)0xFF800000, 0x7FFFFFFF);
            float raw = __int_as_float(cd.x);
            float mr = raw;
            #pragma unroll
            for (int off = 16; off; off >>= 1)
                mr = fmaxf(mr, __shfl_xor_sync(0xffffffffu, mr, off));
            if (lane < n && raw >= mr - FIXMARGIN) {
                bd = exact_dist(xr, xsq, cd.y);
                bi = cd.y;
            }
        } else {
            for (int c = lane; c < KCB; c += 32) {
                float dist = exact_dist(xr, xsq, c);
                if (dist > bd) { bd = dist; bi = c; }
            }
        }
        #pragma unroll
        for (int off = 16; off; off >>= 1) {
            float ov = __shfl_xor_sync(0xffffffffu, bd, off);
            int   oi = __shfl_xor_sync(0xffffffffu, bi, off);
            if (ov > bd || (ov == bd && oi < bi)) { bd = ov; bi = oi; }
        }
        if (lane == 0) {
            g_ind[row] = bi;
            g_slot[row] = atomicAdd(&g_cnti[bi], 1);
            out_ind[row] = (float)bi;
        }
    }
}

// ---------------------------------------------------------------------------
__global__ void k_scan(const float* __restrict__ cs, float* __restrict__ out_ncs) {
    __shared__ int sh[1024];
    __shared__ float ws[32];
    int tid = threadIdx.x;
    int c = g_cnti[tid];
    sh[tid] = c;
    __syncthreads();
    for (int off = 1; off < 1024; off <<= 1) {
        int t = (tid >= off) ? sh[tid - off] : 0;
        __syncthreads();
        sh[tid] += t;
        __syncthreads();
    }
    g_off[tid] = sh[tid] - c;

    float v = __fadd_rn(__fmul_rn(cs[tid], 0.99f), __fmul_rn(0.01f, (float)c));
    out_ncs[tid] = v;
    float s = v;
    #pragma unroll
    for (int off = 16; off; off >>= 1)
        s += __shfl_xor_sync(0xffffffffu, s, off);
    if ((tid & 31) == 0) ws[tid >> 5] = s;
    __syncthreads();
    if (tid < 32) {
        float t = ws[tid];
        #pragma unroll
        for (int off = 16; off; off >>= 1)
            t += __shfl_xor_sync(0xffffffffu, t, off);
        if (tid == 0) ws[0] = t;
    }
    __syncthreads();
    float total = ws[0];
    g_smoothed[tid] = __fmul_rn(
        __fdiv_rn(__fadd_rn(v, 1e-5f), __fadd_rn(total, 0.01024f)), total);
}

__global__ void k_place() {
    int row = blockIdx.x * 256 + threadIdx.x;
    g_rowlist[g_off[g_ind[row]] + g_slot[row]] = row;
}

__global__ void k_gather(const float* __restrict__ x,
                         const float* __restrict__ ea,
                         float* __restrict__ out_nea,
                         float* __restrict__ out_ne) {
    __shared__ int rs[128];
    int k = blockIdx.x, d = threadIdx.x;
    int cnt = g_cnti[k], off = g_off[k];
    float s = 0.0f;
    for (int base = 0; base < cnt; base += 128) {
        int m = min(128, cnt - base);
        __syncthreads();
        if (d < m) rs[d] = g_rowlist[off + base + d];
        __syncthreads();
        for (int i = 0; i < m; i++)
            s += x[(size_t)rs[i] * DIM + d];
    }
    float r = __fadd_rn(__fmul_rn(ea[k * DIM + d], 0.99f), __fmul_rn(0.01f, s));
    out_nea[k * DIM + d] = r;
    out_ne[k * DIM + d] = __fdiv_rn(r, g_smoothed[k]);
}

__global__ __launch_bounds__(256)
void k_quant(const float* __restrict__ embed,
             float* __restrict__ out_q) {
    int w = (blockIdx.x * 256 + threadIdx.x) >> 5;
    int lane = threadIdx.x & 31;
    int ind = g_ind[w];
    float4 e4 = ((const float4*)(embed + (size_t)ind * DIM))[lane];
    ((float4*)(out_q + (size_t)w * DIM))[lane] = e4;
}

// ---------------------------------------------------------------------------
extern "C" void kernel_launch(void* const* d_in, const int* in_sizes, int n_in,
                              void* d_out, int out_size) {
    const float* x     = (const float*)d_in[0];
    const float* embed = (const float*)d_in[1];
    const float* cs    = (const float*)d_in[2];
    const float* ea    = (const float*)d_in[3];

    float* out     = (float*)d_out;
    float* out_q   = out;
    float* out_ind = out + (size_t)N_ROWS * DIM;
    float* out_ncs = out_ind + N_ROWS;
    float* out_nea = out_ncs + KCB;
    float* out_ne  = out_nea + (size_t)KCB * DIM;

    static bool attr_done = false;
    if (!attr_done) {
        cudaFuncSetAttribute(k_main, cudaFuncAttributeMaxDynamicSharedMemorySize,
                             SMEM_BYTES);
        attr_done = true;
    }

    k_pre<<<KCB, DIM>>>(embed);
    k_esq<<<KCB / 128, 128>>>(embed);
    k_main<<<N_ROWS / BM, 256, SMEM_BYTES>>>(x);
    k_fix1<<<N_ROWS / 256, 256>>>(out_ind);
    k_fix2<<<296, 256>>>(x, out_ind);
    k_scan<<<1, 1024>>>(cs, out_ncs);
    k_place<<<N_ROWS / 256, 256>>>();
    k_gather<<<KCB, DIM>>>(x, ea, out_nea, out_ne);
    k_quant<<<(N_ROWS * 32) / 256, 256>>>(embed, out_q);
}

// round 13
// speedup vs baseline: 3.1349x; 3.1349x over previous
#include <cuda_runtime.h>
#include <cuda_bf16.h>
#include <cstdint>

#define N_ROWS 131072
#define DIM 128
#define KCB 1024
#define BM 128
#define PRECF 1e7f
#define NCAND 16
#define MARGIN 6e-2f
#define FIXMARGIN 4.5e-2f

// padded row: 128 bf16 = 256B + 16B pad = 272B (conflict-free ldmatrix)
#define ROWB 272
#define TILEB (BM * ROWB)          // 34816 bytes: one 128x128 bf16 tile

// smem layout (109056 total -> 2 CTAs/SM)
#define SM_XH  0
#define SM_E   TILEB                       // + buf*TILEB, 2 buffers
#define SM_ESQ (3 * TILEB)                 // 1024 floats
#define SM_CNT (SM_ESQ + 4096)             // 128 ints
#define SMEM_BYTES (SM_CNT + 512)          // 109056

// ---- device scratch ----
__device__ int     g_ind[N_ROWS];
__device__ float   g_esq[KCB];
__device__ float   g_Eq[KCB * DIM];          // qt(E), natural layout (fix path)
__device__ uint8_t g_Ehi[8 * TILEB];         // per chunk: bf16-hi tile, padded
__device__ int2    g_cand[(size_t)N_ROWS * NCAND];
__device__ int     g_ncand[N_ROWS];
__device__ int     g_work[N_ROWS];
__device__ int     g_nwork;
__device__ int     g_cnti[KCB];
__device__ int     g_off[KCB];
__device__ int     g_slot[N_ROWS];
__device__ int     g_rowlist[N_ROWS];
__device__ float   g_smoothed[KCB];

__device__ __forceinline__ float qt(float t) {
    return __fdiv_rn(rintf(__fmul_rn(t, PRECF)), PRECF);
}
__device__ __forceinline__ uint32_t smem_u32(const void* p) {
    return (uint32_t)__cvta_generic_to_shared(p);
}
__device__ __forceinline__ void cp16(uint32_t dst, const void* src) {
    asm volatile("cp.async.cg.shared.global [%0], [%1], 16;" :: "r"(dst), "l"(src));
}
__device__ __forceinline__ void cp_commit() { asm volatile("cp.async.commit_group;"); }
template <int N>
__device__ __forceinline__ void cp_wait() {
    asm volatile("cp.async.wait_group %0;" :: "n"(N));
}
__device__ __forceinline__ void ldsm4(uint32_t* r, uint32_t addr) {
    asm volatile("ldmatrix.sync.aligned.m8n8.x4.shared.b16 {%0,%1,%2,%3},[%4];"
                 : "=r"(r[0]), "=r"(r[1]), "=r"(r[2]), "=r"(r[3]) : "r"(addr));
}
__device__ __forceinline__ void mma_bf16(float* d, const uint32_t* a,
                                         uint32_t b0, uint32_t b1) {
    asm volatile(
        "mma.sync.aligned.m16n8k16.row.col.f32.bf16.bf16.f32 "
        "{%0,%1,%2,%3},{%4,%5,%6,%7},{%8,%9},{%0,%1,%2,%3};"
        : "+f"(d[0]), "+f"(d[1]), "+f"(d[2]), "+f"(d[3])
        : "r"(a[0]), "r"(a[1]), "r"(a[2]), "r"(a[3]), "r"(b0), "r"(b1));
}

// exact R4 GPU-shape x_sq over one 128-float row
__device__ float xsq_row(const float* __restrict__ v) {
    float s[32];
    #pragma unroll
    for (int t = 0; t < 32; t++) {
        float a0 = v[2 * t], a1 = v[2 * t + 1];
        float b0 = v[64 + 2 * t], b1 = v[64 + 2 * t + 1];
        float p0 = __fmaf_rn(b0, b0, __fmaf_rn(a0, a0, 0.0f));
        float p1 = __fmaf_rn(b1, b1, __fmaf_rn(a1, a1, 0.0f));
        s[t] = __fadd_rn(p0, p1);
    }
    #pragma unroll
    for (int off = 16; off; off >>= 1)
        #pragma unroll
        for (int t = 0; t < off; t++)
            s[t] = __fadd_rn(s[t], s[t + off]);
    return qt(s[0]);
}

// exact dist for one (row, code): bit-identical to the R4 chain
__device__ __forceinline__ float exact_dist(const float* __restrict__ xr,
                                            float xsq, int c) {
    const float* e = g_Eq + (size_t)c * DIM;
    float dot = 0.0f;
    #pragma unroll 8
    for (int d = 0; d < DIM; d++)
        dot = __fmaf_rn(xr[d], e[d], dot);
    float c3 = qt(__fmul_rn(qt(dot), 2.0f));
    float S  = qt(__fadd_rn(xsq, g_esq[c]));
    return -qt(__fsub_rn(S, c3));
}

// ---------------------------------------------------------------------------
// k_pre: qt(E); bf16-hi into padded chunk tiles; zero counters
// ---------------------------------------------------------------------------
__global__ void k_pre(const float* __restrict__ embed) {
    int k = blockIdx.x;
    int d = threadIdx.x;
    float eq = qt(embed[k * DIM + d]);
    g_Eq[k * DIM + d] = eq;
    *(__nv_bfloat16*)(g_Ehi + (size_t)(k >> 7) * TILEB + (k & 127) * ROWB + d * 2) =
        __float2bfloat16(eq);
    if (d == 0) {
        g_cnti[k] = 0;
        if (k == 0) g_nwork = 0;
    }
}

// ---------------------------------------------------------------------------
// k_esq: XLA:GPU column-reduction emulation (bit-exact, proven R4)
// ---------------------------------------------------------------------------
__global__ void k_esq(const float* __restrict__ embed) {
    int k = blockIdx.x * 128 + threadIdx.x;
    const float* row = embed + (size_t)k * DIM;
    float s[32];
    #pragma unroll
    for (int j = 0; j < 32; j++) {
        float p = 0.0f;
        #pragma unroll
        for (int i = 0; i < 4; i++) {
            float e = qt(row[j + 32 * i]);
            p = __fmaf_rn(e, e, p);
        }
        s[j] = p;
    }
    #pragma unroll
    for (int off = 16; off; off >>= 1)
        #pragma unroll
        for (int t = 0; t < off; t++)
            s[t] = __fadd_rn(s[t], s[t + off]);
    g_esq[k] = qt(s[0]);
}

// ---------------------------------------------------------------------------
// k_main: HMMA bf16 1-term screen (bf16(x)·bf16(e)) + in-register argmax
// 256 threads = 8 warps, warp w owns rows w*16..w*16+15 x all codes
// (byte-identical to the proven R9/R11 config: 2 CTA/SM, no spills)
// ---------------------------------------------------------------------------
__global__ __launch_bounds__(256, 2)
void k_main(const float* __restrict__ x) {
    extern __shared__ char smem[];
    uint32_t sb = smem_u32(smem);
    float* esq_s = (float*)(smem + SM_ESQ);
    int*   cnt_s = (int*)(smem + SM_CNT);

    int tid = threadIdx.x;
    int warp = tid >> 5;
    int lane = tid & 31;
    int g = lane >> 2, tig = lane & 3;
    int row0 = blockIdx.x * BM;

    if (tid < BM) cnt_s[tid] = 0;

    // prefetch E chunks 0 and 1
    #pragma unroll
    for (int b = 0; b < 2; b++) {
        #pragma unroll
        for (int s = 0; s < 9; s++) {
            int gr = tid + s * 256;
            if (gr < TILEB / 16)
                cp16(sb + SM_E + b * TILEB + gr * 16,
                     g_Ehi + (size_t)b * TILEB + gr * 16);
        }
        cp_commit();
    }

    // X load -> bf16 hi tile
    #pragma unroll
    for (int s = 0; s < 32; s++) {
        int p = tid + s * 256;                 // 8192 pairs
        int row = p >> 6, d = (p & 63) * 2;
        float2 v = *(const float2*)(x + (size_t)(row0 + row) * DIM + d);
        *(__nv_bfloat162*)(smem + SM_XH + row * ROWB + d * 2) =
            __nv_bfloat162(__float2bfloat16(v.x), __float2bfloat16(v.y));
    }
    #pragma unroll
    for (int s = 0; s < 4; s++) esq_s[tid + s * 256] = g_esq[tid + s * 256];
    __syncthreads();

    // A fragments (X hi), resident for all chunks: 8 ksteps x 4 regs
    uint32_t ah[8][4];
    {
        uint32_t abase = sb + SM_XH + (warp * 16 + (lane & 15)) * ROWB
                       + (lane >> 4) * 16;
        #pragma unroll
        for (int s = 0; s < 8; s++) ldsm4(ah[s], abase + s * 32);
    }

    float bestA = -3.4e38f, bestB = -3.4e38f;
    int rowA = warp * 16 + g, rowB = rowA + 8;

    for (int kc = 0; kc < 8; kc++) {
        if (kc < 7) cp_wait<1>(); else cp_wait<0>();
        __syncthreads();
        uint32_t eb = sb + SM_E + (kc & 1) * TILEB;

        #pragma unroll
        for (int h = 0; h < 2; h++) {          // 64 codes per half
            float acc[8][4];
            #pragma unroll
            for (int n = 0; n < 8; n++)
                #pragma unroll
                for (int j = 0; j < 4; j++) acc[n][j] = 0.0f;

            #pragma unroll
            for (int pp = 0; pp < 2; pp++) {
                int nt0 = pp * 4;
                uint32_t b0a = eb + (uint32_t)((h * 64 + pp * 32 + (lane & 7)
                                 + ((lane & 16) ? 8 : 0)) * ROWB)
                             + ((lane >> 3) & 1) * 16;
                uint32_t b1a = b0a + 16 * ROWB;
                #pragma unroll
                for (int s = 0; s < 8; s++) {
                    uint32_t bh0[4], bh1[4];
                    ldsm4(bh0, b0a + s * 32);
                    ldsm4(bh1, b1a + s * 32);
                    mma_bf16(acc[nt0 + 0], ah[s], bh0[0], bh0[1]);
                    mma_bf16(acc[nt0 + 1], ah[s], bh0[2], bh0[3]);
                    mma_bf16(acc[nt0 + 2], ah[s], bh1[0], bh1[1]);
                    mma_bf16(acc[nt0 + 3], ah[s], bh1[2], bh1[3]);
                }
            }

            // epilogue: scores, per-thread local max, quad max, candidates
            float mA = -3.4e38f, mB = -3.4e38f;
            #pragma unroll
            for (int nt = 0; nt < 8; nt++) {
                int c = kc * 128 + h * 64 + nt * 8 + tig * 2;
                float e0 = esq_s[c], e1 = esq_s[c + 1];
                acc[nt][0] = __fmaf_rn(2.0f, acc[nt][0], -e0);
                acc[nt][1] = __fmaf_rn(2.0f, acc[nt][1], -e1);
                acc[nt][2] = __fmaf_rn(2.0f, acc[nt][2], -e0);
                acc[nt][3] = __fmaf_rn(2.0f, acc[nt][3], -e1);
                mA = fmaxf(mA, fmaxf(acc[nt][0], acc[nt][1]));
                mB = fmaxf(mB, fmaxf(acc[nt][2], acc[nt][3]));
            }
            float mA_loc = mA, mB_loc = mB;    // pre-shuffle thread-local maxes
            mA = fmaxf(mA, __shfl_xor_sync(0xffffffffu, mA, 1));
            mA = fmaxf(mA, __shfl_xor_sync(0xffffffffu, mA, 2));
            mB = fmaxf(mB, __shfl_xor_sync(0xffffffffu, mB, 1));
            mB = fmaxf(mB, __shfl_xor_sync(0xffffffffu, mB, 2));
            bestA = fmaxf(bestA, mA);
            bestB = fmaxf(bestB, mB);
            float thrA = bestA - MARGIN, thrB = bestB - MARGIN;

            // early-skip: only threads holding a potential candidate scan
            if (mA_loc >= thrA || mB_loc >= thrB) {
                #pragma unroll
                for (int nt = 0; nt < 8; nt++) {
                    int c = kc * 128 + h * 64 + nt * 8 + tig * 2;
                    #pragma unroll
                    for (int j = 0; j < 4; j++) {
                        float sc = acc[nt][j];
                        bool isB = (j >= 2);
                        if (sc >= (isB ? thrB : thrA)) {
                            int r = isB ? rowB : rowA;
                            int slot = atomicAdd(&cnt_s[r], 1);
                            if (slot < NCAND)
                                g_cand[(size_t)(row0 + r) * NCAND + slot] =
                                    make_int2(__float_as_int(sc), c + (j & 1));
                        }
                    }
                }
            }
        }

        __syncthreads();
        if (kc + 2 < 8) {
            #pragma unroll
            for (int s = 0; s < 9; s++) {
                int gr = tid + s * 256;
                if (gr < TILEB / 16)
                    cp16(sb + SM_E + (kc & 1) * TILEB + gr * 16,
                         g_Ehi + (size_t)(kc + 2) * TILEB + gr * 16);
            }
            cp_commit();
        }
    }

    __syncthreads();
    if (tid < BM) g_ncand[row0 + tid] = cnt_s[tid];
}

// ---------------------------------------------------------------------------
// k_fix1: resolve single-qualifier rows (also assigns bucket slot + out_ind);
// push the rest to the worklist
// ---------------------------------------------------------------------------
__global__ void k_fix1(float* __restrict__ out_ind) {
    int row = blockIdx.x * 256 + threadIdx.x;
    int n = g_ncand[row];
    if (n <= NCAND) {
        const int2* cand = &g_cand[(size_t)row * NCAND];
        float mr = -3.4e38f;
        for (int s = 0; s < n; s++)
            mr = fmaxf(mr, __int_as_float(cand[s].x));
        float thr = mr - FIXMARGIN;
        int nq = 0, only = 0;
        for (int s = 0; s < n; s++)
            if (__int_as_float(cand[s].x) >= thr) { nq++; only = cand[s].y; }
        if (nq <= 1) {
            g_ind[row] = only;
            g_slot[row] = atomicAdd(&g_cnti[only], 1);
            out_ind[row] = (float)only;
            return;
        }
    }
    int w = atomicAdd(&g_nwork, 1);
    g_work[w] = row;
}

// ---------------------------------------------------------------------------
// k_fix2: warp per work-row; lane per candidate, bit-exact R4 chain
// ---------------------------------------------------------------------------
__global__ __launch_bounds__(256)
void k_fix2(const float* __restrict__ x, float* __restrict__ out_ind) {
    int gw = (blockIdx.x * 256 + threadIdx.x) >> 5;
    int lane = threadIdx.x & 31;
    int nwarps = gridDim.x * 8;
    int nwork = g_nwork;

    for (int i = gw; i < nwork; i += nwarps) {
        int row = g_work[i];
        const float* xr = x + (size_t)row * DIM;
        int n = g_ncand[row];
        float xsq = xsq_row(xr);

        float bd = -3.4e38f;
        int bi = 0x7FFFFFFF;
        if (n <= NCAND) {
            int2 cd = (lane < n) ? g_cand[(size_t)row * NCAND + lane]
                                 : make_int2((int)0xFF800000, 0x7FFFFFFF);
            float raw = __int_as_float(cd.x);
            float mr = raw;
            #pragma unroll
            for (int off = 16; off; off >>= 1)
                mr = fmaxf(mr, __shfl_xor_sync(0xffffffffu, mr, off));
            if (lane < n && raw >= mr - FIXMARGIN) {
                bd = exact_dist(xr, xsq, cd.y);
                bi = cd.y;
            }
        } else {
            for (int c = lane; c < KCB; c += 32) {
                float dist = exact_dist(xr, xsq, c);
                if (dist > bd) { bd = dist; bi = c; }
            }
        }
        #pragma unroll
        for (int off = 16; off; off >>= 1) {
            float ov = __shfl_xor_sync(0xffffffffu, bd, off);
            int   oi = __shfl_xor_sync(0xffffffffu, bi, off);
            if (ov > bd || (ov == bd && oi < bi)) { bd = ov; bi = oi; }
        }
        if (lane == 0) {
            g_ind[row] = bi;
            g_slot[row] = atomicAdd(&g_cnti[bi], 1);
            out_ind[row] = (float)bi;
        }
    }
}

// ---------------------------------------------------------------------------
__global__ void k_scan(const float* __restrict__ cs, float* __restrict__ out_ncs) {
    __shared__ int sh[1024];
    __shared__ float ws[32];
    int tid = threadIdx.x;
    int c = g_cnti[tid];
    sh[tid] = c;
    __syncthreads();
    for (int off = 1; off < 1024; off <<= 1) {
        int t = (tid >= off) ? sh[tid - off] : 0;
        __syncthreads();
        sh[tid] += t;
        __syncthreads();
    }
    g_off[tid] = sh[tid] - c;

    float v = __fadd_rn(__fmul_rn(cs[tid], 0.99f), __fmul_rn(0.01f, (float)c));
    out_ncs[tid] = v;
    float s = v;
    #pragma unroll
    for (int off = 16; off; off >>= 1)
        s += __shfl_xor_sync(0xffffffffu, s, off);
    if ((tid & 31) == 0) ws[tid >> 5] = s;
    __syncthreads();
    if (tid < 32) {
        float t = ws[tid];
        #pragma unroll
        for (int off = 16; off; off >>= 1)
            t += __shfl_xor_sync(0xffffffffu, t, off);
        if (tid == 0) ws[0] = t;
    }
    __syncthreads();
    float total = ws[0];
    g_smoothed[tid] = __fmul_rn(
        __fdiv_rn(__fadd_rn(v, 1e-5f), __fadd_rn(total, 0.01024f)), total);
}

// ---------------------------------------------------------------------------
// k_quant: gather for quantize + fused rowlist placement (was k_place)
// ---------------------------------------------------------------------------
__global__ __launch_bounds__(256)
void k_quant(const float* __restrict__ embed,
             float* __restrict__ out_q) {
    int w = (blockIdx.x * 256 + threadIdx.x) >> 5;
    int lane = threadIdx.x & 31;
    int ind = g_ind[w];
    float4 e4 = ((const float4*)(embed + (size_t)ind * DIM))[lane];
    ((float4*)(out_q + (size_t)w * DIM))[lane] = e4;
    if (lane == 0)
        g_rowlist[g_off[ind] + g_slot[w]] = w;
}

__global__ void k_gather(const float* __restrict__ x,
                         const float* __restrict__ ea,
                         float* __restrict__ out_nea,
                         float* __restrict__ out_ne) {
    __shared__ int rs[128];
    int k = blockIdx.x, d = threadIdx.x;
    int cnt = g_cnti[k], off = g_off[k];
    float s = 0.0f;
    for (int base = 0; base < cnt; base += 128) {
        int m = min(128, cnt - base);
        __syncthreads();
        if (d < m) rs[d] = g_rowlist[off + base + d];
        __syncthreads();
        for (int i = 0; i < m; i++)
            s += x[(size_t)rs[i] * DIM + d];
    }
    float r = __fadd_rn(__fmul_rn(ea[k * DIM + d], 0.99f), __fmul_rn(0.01f, s));
    out_nea[k * DIM + d] = r;
    out_ne[k * DIM + d] = __fdiv_rn(r, g_smoothed[k]);
}

// ---------------------------------------------------------------------------
extern "C" void kernel_launch(void* const* d_in, const int* in_sizes, int n_in,
                              void* d_out, int out_size) {
    const float* x     = (const float*)d_in[0];
    const float* embed = (const float*)d_in[1];
    const float* cs    = (const float*)d_in[2];
    const float* ea    = (const float*)d_in[3];

    float* out     = (float*)d_out;
    float* out_q   = out;
    float* out_ind = out + (size_t)N_ROWS * DIM;
    float* out_ncs = out_ind + N_ROWS;
    float* out_nea = out_ncs + KCB;
    float* out_ne  = out_nea + (size_t)KCB * DIM;

    static bool attr_done = false;
    if (!attr_done) {
        cudaFuncSetAttribute(k_main, cudaFuncAttributeMaxDynamicSharedMemorySize,
                             SMEM_BYTES);
        attr_done = true;
    }

    k_pre<<<KCB, DIM>>>(embed);
    k_esq<<<KCB / 128, 128>>>(embed);
    k_main<<<N_ROWS / BM, 256, SMEM_BYTES>>>(x);
    k_fix1<<<N_ROWS / 256, 256>>>(out_ind);
    k_fix2<<<296, 256>>>(x, out_ind);
    k_scan<<<1, 1024>>>(cs, out_ncs);
    k_quant<<<(N_ROWS * 32) / 256, 256>>>(embed, out_q);
    k_gather<<<KCB, DIM>>>(x, ea, out_nea, out_ne);
}

// round 14
// speedup vs baseline: 3.3439x; 1.0666x over previous
#include <cuda_runtime.h>
#include <cuda_bf16.h>
#include <cstdint>

#define N_ROWS 131072
#define DIM 128
#define KCB 1024
#define BM 128
#define PRECF 1e7f
#define NCAND 16
#define MARGIN 6e-2f
#define FIXMARGIN 4.5e-2f

// padded row: 128 bf16 = 256B + 16B pad = 272B (conflict-free ldmatrix)
#define ROWB 272
#define TILEB (BM * ROWB)          // 34816 bytes: one 128x128 bf16 tile

// smem layout (109056 total -> 2 CTAs/SM)
#define SM_XH  0
#define SM_E   TILEB                       // + buf*TILEB, 2 buffers
#define SM_ESQ (3 * TILEB)                 // 1024 floats
#define SM_CNT (SM_ESQ + 4096)             // 128 ints
#define SMEM_BYTES (SM_CNT + 512)          // 109056

// ---- device scratch ----
__device__ int     g_ind[N_ROWS];
__device__ float   g_esq[KCB];
__device__ float   g_Eq[KCB * DIM];          // qt(E), natural layout (fix path)
__device__ uint8_t g_Ehi[8 * TILEB];         // per chunk: bf16-hi tile, padded
__device__ int2    g_cand[(size_t)N_ROWS * NCAND];
__device__ int     g_ncand[N_ROWS];
__device__ int     g_work[N_ROWS];
__device__ int     g_nwork;
__device__ int     g_cnti[KCB];
__device__ int     g_off[KCB];
__device__ int     g_slot[N_ROWS];
__device__ int     g_rowlist[N_ROWS];
__device__ float   g_smoothed[KCB];

__device__ __forceinline__ float qt(float t) {
    return __fdiv_rn(rintf(__fmul_rn(t, PRECF)), PRECF);
}
__device__ __forceinline__ uint32_t smem_u32(const void* p) {
    return (uint32_t)__cvta_generic_to_shared(p);
}
__device__ __forceinline__ void cp16(uint32_t dst, const void* src) {
    asm volatile("cp.async.cg.shared.global [%0], [%1], 16;" :: "r"(dst), "l"(src));
}
__device__ __forceinline__ void cp_commit() { asm volatile("cp.async.commit_group;"); }
template <int N>
__device__ __forceinline__ void cp_wait() {
    asm volatile("cp.async.wait_group %0;" :: "n"(N));
}
__device__ __forceinline__ void ldsm4(uint32_t* r, uint32_t addr) {
    asm volatile("ldmatrix.sync.aligned.m8n8.x4.shared.b16 {%0,%1,%2,%3},[%4];"
                 : "=r"(r[0]), "=r"(r[1]), "=r"(r[2]), "=r"(r[3]) : "r"(addr));
}
__device__ __forceinline__ void mma_bf16(float* d, const uint32_t* a,
                                         uint32_t b0, uint32_t b1) {
    asm volatile(
        "mma.sync.aligned.m16n8k16.row.col.f32.bf16.bf16.f32 "
        "{%0,%1,%2,%3},{%4,%5,%6,%7},{%8,%9},{%0,%1,%2,%3};"
        : "+f"(d[0]), "+f"(d[1]), "+f"(d[2]), "+f"(d[3])
        : "r"(a[0]), "r"(a[1]), "r"(a[2]), "r"(a[3]), "r"(b0), "r"(b1));
}

// exact R4 GPU-shape x_sq over one 128-float row
__device__ float xsq_row(const float* __restrict__ v) {
    float s[32];
    #pragma unroll
    for (int t = 0; t < 32; t++) {
        float a0 = v[2 * t], a1 = v[2 * t + 1];
        float b0 = v[64 + 2 * t], b1 = v[64 + 2 * t + 1];
        float p0 = __fmaf_rn(b0, b0, __fmaf_rn(a0, a0, 0.0f));
        float p1 = __fmaf_rn(b1, b1, __fmaf_rn(a1, a1, 0.0f));
        s[t] = __fadd_rn(p0, p1);
    }
    #pragma unroll
    for (int off = 16; off; off >>= 1)
        #pragma unroll
        for (int t = 0; t < off; t++)
            s[t] = __fadd_rn(s[t], s[t + off]);
    return qt(s[0]);
}

// exact dist for one (row, code): bit-identical to the R4 chain
__device__ __forceinline__ float exact_dist(const float* __restrict__ xr,
                                            float xsq, int c) {
    const float* e = g_Eq + (size_t)c * DIM;
    float dot = 0.0f;
    #pragma unroll 8
    for (int d = 0; d < DIM; d++)
        dot = __fmaf_rn(xr[d], e[d], dot);
    float c3 = qt(__fmul_rn(qt(dot), 2.0f));
    float S  = qt(__fadd_rn(xsq, g_esq[c]));
    return -qt(__fsub_rn(S, c3));
}

// ---------------------------------------------------------------------------
// k_pre: qt(E) + bf16-hi tiles + fused e_sq (exact column-reduction via
// shfl_down tree, same s[t]=s[t]+s[t+off] ordering as the proven k_esq)
// ---------------------------------------------------------------------------
__global__ void k_pre(const float* __restrict__ embed) {
    int k = blockIdx.x;
    int d = threadIdx.x;
    float eq = qt(embed[k * DIM + d]);
    g_Eq[k * DIM + d] = eq;
    *(__nv_bfloat16*)(g_Ehi + (size_t)(k >> 7) * TILEB + (k & 127) * ROWB + d * 2) =
        __float2bfloat16(eq);
    if (d < 32) {
        float p = 0.0f;
        #pragma unroll
        for (int i = 0; i < 4; i++) {
            float e = qt(embed[k * DIM + d + 32 * i]);
            p = __fmaf_rn(e, e, p);
        }
        #pragma unroll
        for (int off = 16; off; off >>= 1)
            p = __fadd_rn(p, __shfl_down_sync(0xffffffffu, p, off));
        if (d == 0) {
            g_esq[k] = qt(p);
            g_cnti[k] = 0;
            if (k == 0) g_nwork = 0;
        }
    }
}

// ---------------------------------------------------------------------------
// k_main: HMMA bf16 1-term screen + in-register argmax + fused fix1 tail
// 256 threads = 8 warps, warp w owns rows w*16..w*16+15 x all codes
// ---------------------------------------------------------------------------
__global__ __launch_bounds__(256, 2)
void k_main(const float* __restrict__ x, float* __restrict__ out_ind) {
    extern __shared__ char smem[];
    uint32_t sb = smem_u32(smem);
    float* esq_s = (float*)(smem + SM_ESQ);
    int*   cnt_s = (int*)(smem + SM_CNT);

    int tid = threadIdx.x;
    int warp = tid >> 5;
    int lane = tid & 31;
    int g = lane >> 2, tig = lane & 3;
    int row0 = blockIdx.x * BM;

    if (tid < BM) cnt_s[tid] = 0;

    // prefetch E chunks 0 and 1
    #pragma unroll
    for (int b = 0; b < 2; b++) {
        #pragma unroll
        for (int s = 0; s < 9; s++) {
            int gr = tid + s * 256;
            if (gr < TILEB / 16)
                cp16(sb + SM_E + b * TILEB + gr * 16,
                     g_Ehi + (size_t)b * TILEB + gr * 16);
        }
        cp_commit();
    }

    // X load -> bf16 hi tile
    #pragma unroll
    for (int s = 0; s < 32; s++) {
        int p = tid + s * 256;                 // 8192 pairs
        int row = p >> 6, d = (p & 63) * 2;
        float2 v = *(const float2*)(x + (size_t)(row0 + row) * DIM + d);
        *(__nv_bfloat162*)(smem + SM_XH + row * ROWB + d * 2) =
            __nv_bfloat162(__float2bfloat16(v.x), __float2bfloat16(v.y));
    }
    #pragma unroll
    for (int s = 0; s < 4; s++) esq_s[tid + s * 256] = g_esq[tid + s * 256];
    __syncthreads();

    // A fragments (X hi), resident for all chunks: 8 ksteps x 4 regs
    uint32_t ah[8][4];
    {
        uint32_t abase = sb + SM_XH + (warp * 16 + (lane & 15)) * ROWB
                       + (lane >> 4) * 16;
        #pragma unroll
        for (int s = 0; s < 8; s++) ldsm4(ah[s], abase + s * 32);
    }

    float bestA = -3.4e38f, bestB = -3.4e38f;
    int rowA = warp * 16 + g, rowB = rowA + 8;

    for (int kc = 0; kc < 8; kc++) {
        if (kc < 7) cp_wait<1>(); else cp_wait<0>();
        __syncthreads();
        uint32_t eb = sb + SM_E + (kc & 1) * TILEB;

        #pragma unroll
        for (int h = 0; h < 2; h++) {          // 64 codes per half
            float acc[8][4];
            #pragma unroll
            for (int n = 0; n < 8; n++)
                #pragma unroll
                for (int j = 0; j < 4; j++) acc[n][j] = 0.0f;

            #pragma unroll
            for (int pp = 0; pp < 2; pp++) {
                int nt0 = pp * 4;
                uint32_t b0a = eb + (uint32_t)((h * 64 + pp * 32 + (lane & 7)
                                 + ((lane & 16) ? 8 : 0)) * ROWB)
                             + ((lane >> 3) & 1) * 16;
                uint32_t b1a = b0a + 16 * ROWB;
                #pragma unroll
                for (int s = 0; s < 8; s++) {
                    uint32_t bh0[4], bh1[4];
                    ldsm4(bh0, b0a + s * 32);
                    ldsm4(bh1, b1a + s * 32);
                    mma_bf16(acc[nt0 + 0], ah[s], bh0[0], bh0[1]);
                    mma_bf16(acc[nt0 + 1], ah[s], bh0[2], bh0[3]);
                    mma_bf16(acc[nt0 + 2], ah[s], bh1[0], bh1[1]);
                    mma_bf16(acc[nt0 + 3], ah[s], bh1[2], bh1[3]);
                }
            }

            // epilogue: scores, per-thread local max, quad max, candidates
            float mA = -3.4e38f, mB = -3.4e38f;
            #pragma unroll
            for (int nt = 0; nt < 8; nt++) {
                int c = kc * 128 + h * 64 + nt * 8 + tig * 2;
                float e0 = esq_s[c], e1 = esq_s[c + 1];
                acc[nt][0] = __fmaf_rn(2.0f, acc[nt][0], -e0);
                acc[nt][1] = __fmaf_rn(2.0f, acc[nt][1], -e1);
                acc[nt][2] = __fmaf_rn(2.0f, acc[nt][2], -e0);
                acc[nt][3] = __fmaf_rn(2.0f, acc[nt][3], -e1);
                mA = fmaxf(mA, fmaxf(acc[nt][0], acc[nt][1]));
                mB = fmaxf(mB, fmaxf(acc[nt][2], acc[nt][3]));
            }
            float mA_loc = mA, mB_loc = mB;    // pre-shuffle thread-local maxes
            mA = fmaxf(mA, __shfl_xor_sync(0xffffffffu, mA, 1));
            mA = fmaxf(mA, __shfl_xor_sync(0xffffffffu, mA, 2));
            mB = fmaxf(mB, __shfl_xor_sync(0xffffffffu, mB, 1));
            mB = fmaxf(mB, __shfl_xor_sync(0xffffffffu, mB, 2));
            bestA = fmaxf(bestA, mA);
            bestB = fmaxf(bestB, mB);
            float thrA = bestA - MARGIN, thrB = bestB - MARGIN;

            // early-skip: only threads holding a potential candidate scan
            if (mA_loc >= thrA || mB_loc >= thrB) {
                #pragma unroll
                for (int nt = 0; nt < 8; nt++) {
                    int c = kc * 128 + h * 64 + nt * 8 + tig * 2;
                    #pragma unroll
                    for (int j = 0; j < 4; j++) {
                        float sc = acc[nt][j];
                        bool isB = (j >= 2);
                        if (sc >= (isB ? thrB : thrA)) {
                            int r = isB ? rowB : rowA;
                            int slot = atomicAdd(&cnt_s[r], 1);
                            if (slot < NCAND)
                                g_cand[(size_t)(row0 + r) * NCAND + slot] =
                                    make_int2(__float_as_int(sc), c + (j & 1));
                        }
                    }
                }
            }
        }

        __syncthreads();
        if (kc + 2 < 8) {
            #pragma unroll
            for (int s = 0; s < 9; s++) {
                int gr = tid + s * 256;
                if (gr < TILEB / 16)
                    cp16(sb + SM_E + (kc & 1) * TILEB + gr * 16,
                         g_Ehi + (size_t)(kc + 2) * TILEB + gr * 16);
            }
            cp_commit();
        }
    }

    // fused fix1 tail: __syncthreads orders this CTA's g_cand global writes
    __syncthreads();
    if (tid < BM) {
        int row = row0 + tid;
        int n = cnt_s[tid];
        g_ncand[row] = n;
        bool resolved = false;
        if (n <= NCAND) {
            const int2* cand = &g_cand[(size_t)row * NCAND];
            float mr = -3.4e38f;
            for (int s = 0; s < n; s++)
                mr = fmaxf(mr, __int_as_float(cand[s].x));
            float thr = mr - FIXMARGIN;
            int nq = 0, only = 0;
            for (int s = 0; s < n; s++)
                if (__int_as_float(cand[s].x) >= thr) { nq++; only = cand[s].y; }
            if (nq <= 1) {
                g_ind[row] = only;
                g_slot[row] = atomicAdd(&g_cnti[only], 1);
                out_ind[row] = (float)only;
                resolved = true;
            }
        }
        if (!resolved) {
            int w = atomicAdd(&g_nwork, 1);
            g_work[w] = row;
        }
    }
}

// ---------------------------------------------------------------------------
// k_fix2: warp per work-row; lane per candidate, bit-exact R4 chain
// ---------------------------------------------------------------------------
__global__ __launch_bounds__(256)
void k_fix2(const float* __restrict__ x, float* __restrict__ out_ind) {
    int gw = (blockIdx.x * 256 + threadIdx.x) >> 5;
    int lane = threadIdx.x & 31;
    int nwarps = gridDim.x * 8;
    int nwork = g_nwork;

    for (int i = gw; i < nwork; i += nwarps) {
        int row = g_work[i];
        const float* xr = x + (size_t)row * DIM;
        int n = g_ncand[row];
        float xsq = xsq_row(xr);

        float bd = -3.4e38f;
        int bi = 0x7FFFFFFF;
        if (n <= NCAND) {
            int2 cd = (lane < n) ? g_cand[(size_t)row * NCAND + lane]
                                 : make_int2((int)0xFF800000, 0x7FFFFFFF);
            float raw = __int_as_float(cd.x);
            float mr = raw;
            #pragma unroll
            for (int off = 16; off; off >>= 1)
                mr = fmaxf(mr, __shfl_xor_sync(0xffffffffu, mr, off));
            if (lane < n && raw >= mr - FIXMARGIN) {
                bd = exact_dist(xr, xsq, cd.y);
                bi = cd.y;
            }
        } else {
            for (int c = lane; c < KCB; c += 32) {
                float dist = exact_dist(xr, xsq, c);
                if (dist > bd) { bd = dist; bi = c; }
            }
        }
        #pragma unroll
        for (int off = 16; off; off >>= 1) {
            float ov = __shfl_xor_sync(0xffffffffu, bd, off);
            int   oi = __shfl_xor_sync(0xffffffffu, bi, off);
            if (ov > bd || (ov == bd && oi < bi)) { bd = ov; bi = oi; }
        }
        if (lane == 0) {
            g_ind[row] = bi;
            g_slot[row] = atomicAdd(&g_cnti[bi], 1);
            out_ind[row] = (float)bi;
        }
    }
}

// ---------------------------------------------------------------------------
__global__ void k_scan(const float* __restrict__ cs, float* __restrict__ out_ncs) {
    __shared__ int sh[1024];
    __shared__ float ws[32];
    int tid = threadIdx.x;
    int c = g_cnti[tid];
    sh[tid] = c;
    __syncthreads();
    for (int off = 1; off < 1024; off <<= 1) {
        int t = (tid >= off) ? sh[tid - off] : 0;
        __syncthreads();
        sh[tid] += t;
        __syncthreads();
    }
    g_off[tid] = sh[tid] - c;

    float v = __fadd_rn(__fmul_rn(cs[tid], 0.99f), __fmul_rn(0.01f, (float)c));
    out_ncs[tid] = v;
    float s = v;
    #pragma unroll
    for (int off = 16; off; off >>= 1)
        s += __shfl_xor_sync(0xffffffffu, s, off);
    if ((tid & 31) == 0) ws[tid >> 5] = s;
    __syncthreads();
    if (tid < 32) {
        float t = ws[tid];
        #pragma unroll
        for (int off = 16; off; off >>= 1)
            t += __shfl_xor_sync(0xffffffffu, t, off);
        if (tid == 0) ws[0] = t;
    }
    __syncthreads();
    float total = ws[0];
    g_smoothed[tid] = __fmul_rn(
        __fdiv_rn(__fadd_rn(v, 1e-5f), __fadd_rn(total, 0.01024f)), total);
}

// ---------------------------------------------------------------------------
// k_quant: gather for quantize + fused rowlist placement
// ---------------------------------------------------------------------------
__global__ __launch_bounds__(256)
void k_quant(const float* __restrict__ embed,
             float* __restrict__ out_q) {
    int w = (blockIdx.x * 256 + threadIdx.x) >> 5;
    int lane = threadIdx.x & 31;
    int ind = g_ind[w];
    float4 e4 = ((const float4*)(embed + (size_t)ind * DIM))[lane];
    ((float4*)(out_q + (size_t)w * DIM))[lane] = e4;
    if (lane == 0)
        g_rowlist[g_off[ind] + g_slot[w]] = w;
}

__global__ void k_gather(const float* __restrict__ x,
                         const float* __restrict__ ea,
                         float* __restrict__ out_nea,
                         float* __restrict__ out_ne) {
    __shared__ int rs[128];
    int k = blockIdx.x, d = threadIdx.x;
    int cnt = g_cnti[k], off = g_off[k];
    float s = 0.0f;
    for (int base = 0; base < cnt; base += 128) {
        int m = min(128, cnt - base);
        __syncthreads();
        if (d < m) rs[d] = g_rowlist[off + base + d];
        __syncthreads();
        for (int i = 0; i < m; i++)
            s += x[(size_t)rs[i] * DIM + d];
    }
    float r = __fadd_rn(__fmul_rn(ea[k * DIM + d], 0.99f), __fmul_rn(0.01f, s));
    out_nea[k * DIM + d] = r;
    out_ne[k * DIM + d] = __fdiv_rn(r, g_smoothed[k]);
}

// ---------------------------------------------------------------------------
extern "C" void kernel_launch(void* const* d_in, const int* in_sizes, int n_in,
                              void* d_out, int out_size) {
    const float* x     = (const float*)d_in[0];
    const float* embed = (const float*)d_in[1];
    const float* cs    = (const float*)d_in[2];
    const float* ea    = (const float*)d_in[3];

    float* out     = (float*)d_out;
    float* out_q   = out;
    float* out_ind = out + (size_t)N_ROWS * DIM;
    float* out_ncs = out_ind + N_ROWS;
    float* out_nea = out_ncs + KCB;
    float* out_ne  = out_nea + (size_t)KCB * DIM;

    static bool attr_done = false;
    if (!attr_done) {
        cudaFuncSetAttribute(k_main, cudaFuncAttributeMaxDynamicSharedMemorySize,
                             SMEM_BYTES);
        attr_done = true;
    }

    k_pre<<<KCB, DIM>>>(embed);
    k_main<<<N_ROWS / BM, 256, SMEM_BYTES>>>(x, out_ind);
    k_fix2<<<296, 256>>>(x, out_ind);
    k_scan<<<1, 1024>>>(cs, out_ncs);
    k_quant<<<(N_ROWS * 32) / 256, 256>>>(embed, out_q);
    k_gather<<<KCB, DIM>>>(x, ea, out_nea, out_ne);
}

// round 15
// speedup vs baseline: 3.3862x; 1.0127x over previous
#include <cuda_runtime.h>
#include <cuda_bf16.h>
#include <cstdint>

#define N_ROWS 131072
#define DIM 128
#define KCB 1024
#define BM 128
#define PRECF 1e7f
#define NCAND 16
#define MARGIN 6e-2f
#define FIXMARGIN 4.5e-2f

// padded row: 128 bf16 = 256B + 16B pad = 272B (conflict-free ldmatrix)
#define ROWB 272
#define TILEB (BM * ROWB)          // 34816 bytes: one 128x128 bf16 tile

// smem layout (109568 total -> 2 CTAs/SM)
#define SM_XH  0
#define SM_E   TILEB                       // + buf*TILEB, 2 buffers
#define SM_ESQ (3 * TILEB)                 // 1024 floats
#define SM_CNT (SM_ESQ + 4096)             // 128 ints
#define SM_IND (SM_CNT + 512)              // 128 ints (resolved ind or -1)
#define SMEM_BYTES (SM_IND + 512)          // 109568

// ---- device scratch ----
__device__ int     g_ind[N_ROWS];
__device__ float   g_esq[KCB];
__device__ float   g_Eq[KCB * DIM];          // qt(E), natural layout (fix path)
__device__ uint8_t g_Ehi[8 * TILEB];         // per chunk: bf16-hi tile, padded
__device__ int2    g_cand[(size_t)N_ROWS * NCAND];
__device__ int     g_ncand[N_ROWS];
__device__ int     g_work[N_ROWS];
__device__ int     g_nwork;
__device__ int     g_cnti[KCB];
__device__ int     g_off[KCB];
__device__ int     g_slot[N_ROWS];
__device__ int     g_rowlist[N_ROWS];
__device__ float   g_smoothed[KCB];

__device__ __forceinline__ float qt(float t) {
    return __fdiv_rn(rintf(__fmul_rn(t, PRECF)), PRECF);
}
__device__ __forceinline__ uint32_t smem_u32(const void* p) {
    return (uint32_t)__cvta_generic_to_shared(p);
}
__device__ __forceinline__ void cp16(uint32_t dst, const void* src) {
    asm volatile("cp.async.cg.shared.global [%0], [%1], 16;" :: "r"(dst), "l"(src));
}
__device__ __forceinline__ void cp_commit() { asm volatile("cp.async.commit_group;"); }
template <int N>
__device__ __forceinline__ void cp_wait() {
    asm volatile("cp.async.wait_group %0;" :: "n"(N));
}
__device__ __forceinline__ void ldsm4(uint32_t* r, uint32_t addr) {
    asm volatile("ldmatrix.sync.aligned.m8n8.x4.shared.b16 {%0,%1,%2,%3},[%4];"
                 : "=r"(r[0]), "=r"(r[1]), "=r"(r[2]), "=r"(r[3]) : "r"(addr));
}
__device__ __forceinline__ void mma_bf16(float* d, const uint32_t* a,
                                         uint32_t b0, uint32_t b1) {
    asm volatile(
        "mma.sync.aligned.m16n8k16.row.col.f32.bf16.bf16.f32 "
        "{%0,%1,%2,%3},{%4,%5,%6,%7},{%8,%9},{%0,%1,%2,%3};"
        : "+f"(d[0]), "+f"(d[1]), "+f"(d[2]), "+f"(d[3])
        : "r"(a[0]), "r"(a[1]), "r"(a[2]), "r"(a[3]), "r"(b0), "r"(b1));
}

// exact R4 GPU-shape x_sq over one 128-float row
__device__ float xsq_row(const float* __restrict__ v) {
    float s[32];
    #pragma unroll
    for (int t = 0; t < 32; t++) {
        float a0 = v[2 * t], a1 = v[2 * t + 1];
        float b0 = v[64 + 2 * t], b1 = v[64 + 2 * t + 1];
        float p0 = __fmaf_rn(b0, b0, __fmaf_rn(a0, a0, 0.0f));
        float p1 = __fmaf_rn(b1, b1, __fmaf_rn(a1, a1, 0.0f));
        s[t] = __fadd_rn(p0, p1);
    }
    #pragma unroll
    for (int off = 16; off; off >>= 1)
        #pragma unroll
        for (int t = 0; t < off; t++)
            s[t] = __fadd_rn(s[t], s[t + off]);
    return qt(s[0]);
}

// exact dist for one (row, code): bit-identical to the R4 chain
__device__ __forceinline__ float exact_dist(const float* __restrict__ xr,
                                            float xsq, int c) {
    const float* e = g_Eq + (size_t)c * DIM;
    float dot = 0.0f;
    #pragma unroll 8
    for (int d = 0; d < DIM; d++)
        dot = __fmaf_rn(xr[d], e[d], dot);
    float c3 = qt(__fmul_rn(qt(dot), 2.0f));
    float S  = qt(__fadd_rn(xsq, g_esq[c]));
    return -qt(__fsub_rn(S, c3));
}

// ---------------------------------------------------------------------------
// k_pre: qt(E) + bf16-hi tiles + fused e_sq (exact column-reduction tree)
// ---------------------------------------------------------------------------
__global__ void k_pre(const float* __restrict__ embed) {
    int k = blockIdx.x;
    int d = threadIdx.x;
    float eq = qt(embed[k * DIM + d]);
    g_Eq[k * DIM + d] = eq;
    *(__nv_bfloat16*)(g_Ehi + (size_t)(k >> 7) * TILEB + (k & 127) * ROWB + d * 2) =
        __float2bfloat16(eq);
    if (d < 32) {
        float p = 0.0f;
        #pragma unroll
        for (int i = 0; i < 4; i++) {
            float e = qt(embed[k * DIM + d + 32 * i]);
            p = __fmaf_rn(e, e, p);
        }
        #pragma unroll
        for (int off = 16; off; off >>= 1)
            p = __fadd_rn(p, __shfl_down_sync(0xffffffffu, p, off));
        if (d == 0) {
            g_esq[k] = qt(p);
            g_cnti[k] = 0;
            if (k == 0) g_nwork = 0;
        }
    }
}

// ---------------------------------------------------------------------------
// k_main: HMMA bf16 1-term screen + in-register argmax + fused fix1 tail
// + fused out_q write for resolved rows (overlaps other CTAs' MMA)
// ---------------------------------------------------------------------------
__global__ __launch_bounds__(256, 2)
void k_main(const float* __restrict__ x, float* __restrict__ out_ind,
            const float* __restrict__ embed, float* __restrict__ out_q) {
    extern __shared__ char smem[];
    uint32_t sb = smem_u32(smem);
    float* esq_s = (float*)(smem + SM_ESQ);
    int*   cnt_s = (int*)(smem + SM_CNT);
    int*   ind_s = (int*)(smem + SM_IND);

    int tid = threadIdx.x;
    int warp = tid >> 5;
    int lane = tid & 31;
    int g = lane >> 2, tig = lane & 3;
    int row0 = blockIdx.x * BM;

    if (tid < BM) cnt_s[tid] = 0;

    // prefetch E chunks 0 and 1
    #pragma unroll
    for (int b = 0; b < 2; b++) {
        #pragma unroll
        for (int s = 0; s < 9; s++) {
            int gr = tid + s * 256;
            if (gr < TILEB / 16)
                cp16(sb + SM_E + b * TILEB + gr * 16,
                     g_Ehi + (size_t)b * TILEB + gr * 16);
        }
        cp_commit();
    }

    // X load -> bf16 hi tile
    #pragma unroll
    for (int s = 0; s < 32; s++) {
        int p = tid + s * 256;                 // 8192 pairs
        int row = p >> 6, d = (p & 63) * 2;
        float2 v = *(const float2*)(x + (size_t)(row0 + row) * DIM + d);
        *(__nv_bfloat162*)(smem + SM_XH + row * ROWB + d * 2) =
            __nv_bfloat162(__float2bfloat16(v.x), __float2bfloat16(v.y));
    }
    #pragma unroll
    for (int s = 0; s < 4; s++) esq_s[tid + s * 256] = g_esq[tid + s * 256];
    __syncthreads();

    // A fragments (X hi), resident for all chunks: 8 ksteps x 4 regs
    uint32_t ah[8][4];
    {
        uint32_t abase = sb + SM_XH + (warp * 16 + (lane & 15)) * ROWB
                       + (lane >> 4) * 16;
        #pragma unroll
        for (int s = 0; s < 8; s++) ldsm4(ah[s], abase + s * 32);
    }

    float bestA = -3.4e38f, bestB = -3.4e38f;
    int rowA = warp * 16 + g, rowB = rowA + 8;

    for (int kc = 0; kc < 8; kc++) {
        if (kc < 7) cp_wait<1>(); else cp_wait<0>();
        __syncthreads();
        uint32_t eb = sb + SM_E + (kc & 1) * TILEB;

        #pragma unroll
        for (int h = 0; h < 2; h++) {          // 64 codes per half
            float acc[8][4];
            #pragma unroll
            for (int n = 0; n < 8; n++)
                #pragma unroll
                for (int j = 0; j < 4; j++) acc[n][j] = 0.0f;

            #pragma unroll
            for (int pp = 0; pp < 2; pp++) {
                int nt0 = pp * 4;
                uint32_t b0a = eb + (uint32_t)((h * 64 + pp * 32 + (lane & 7)
                                 + ((lane & 16) ? 8 : 0)) * ROWB)
                             + ((lane >> 3) & 1) * 16;
                uint32_t b1a = b0a + 16 * ROWB;
                #pragma unroll
                for (int s = 0; s < 8; s++) {
                    uint32_t bh0[4], bh1[4];
                    ldsm4(bh0, b0a + s * 32);
                    ldsm4(bh1, b1a + s * 32);
                    mma_bf16(acc[nt0 + 0], ah[s], bh0[0], bh0[1]);
                    mma_bf16(acc[nt0 + 1], ah[s], bh0[2], bh0[3]);
                    mma_bf16(acc[nt0 + 2], ah[s], bh1[0], bh1[1]);
                    mma_bf16(acc[nt0 + 3], ah[s], bh1[2], bh1[3]);
                }
            }

            // epilogue: scores, per-thread local max, quad max, candidates
            float mA = -3.4e38f, mB = -3.4e38f;
            #pragma unroll
            for (int nt = 0; nt < 8; nt++) {
                int c = kc * 128 + h * 64 + nt * 8 + tig * 2;
                float e0 = esq_s[c], e1 = esq_s[c + 1];
                acc[nt][0] = __fmaf_rn(2.0f, acc[nt][0], -e0);
                acc[nt][1] = __fmaf_rn(2.0f, acc[nt][1], -e1);
                acc[nt][2] = __fmaf_rn(2.0f, acc[nt][2], -e0);
                acc[nt][3] = __fmaf_rn(2.0f, acc[nt][3], -e1);
                mA = fmaxf(mA, fmaxf(acc[nt][0], acc[nt][1]));
                mB = fmaxf(mB, fmaxf(acc[nt][2], acc[nt][3]));
            }
            float mA_loc = mA, mB_loc = mB;    // pre-shuffle thread-local maxes
            mA = fmaxf(mA, __shfl_xor_sync(0xffffffffu, mA, 1));
            mA = fmaxf(mA, __shfl_xor_sync(0xffffffffu, mA, 2));
            mB = fmaxf(mB, __shfl_xor_sync(0xffffffffu, mB, 1));
            mB = fmaxf(mB, __shfl_xor_sync(0xffffffffu, mB, 2));
            bestA = fmaxf(bestA, mA);
            bestB = fmaxf(bestB, mB);
            float thrA = bestA - MARGIN, thrB = bestB - MARGIN;

            // early-skip: only threads holding a potential candidate scan
            if (mA_loc >= thrA || mB_loc >= thrB) {
                #pragma unroll
                for (int nt = 0; nt < 8; nt++) {
                    int c = kc * 128 + h * 64 + nt * 8 + tig * 2;
                    #pragma unroll
                    for (int j = 0; j < 4; j++) {
                        float sc = acc[nt][j];
                        bool isB = (j >= 2);
                        if (sc >= (isB ? thrB : thrA)) {
                            int r = isB ? rowB : rowA;
                            int slot = atomicAdd(&cnt_s[r], 1);
                            if (slot < NCAND)
                                g_cand[(size_t)(row0 + r) * NCAND + slot] =
                                    make_int2(__float_as_int(sc), c + (j & 1));
                        }
                    }
                }
            }
        }

        __syncthreads();
        if (kc + 2 < 8) {
            #pragma unroll
            for (int s = 0; s < 9; s++) {
                int gr = tid + s * 256;
                if (gr < TILEB / 16)
                    cp16(sb + SM_E + (kc & 1) * TILEB + gr * 16,
                         g_Ehi + (size_t)(kc + 2) * TILEB + gr * 16);
            }
            cp_commit();
        }
    }

    // fused fix1 tail: __syncthreads orders this CTA's g_cand global writes
    __syncthreads();
    if (tid < BM) {
        int row = row0 + tid;
        int n = cnt_s[tid];
        g_ncand[row] = n;
        int resolved = -1;
        if (n <= NCAND) {
            const int2* cand = &g_cand[(size_t)row * NCAND];
            float mr = -3.4e38f;
            for (int s = 0; s < n; s++)
                mr = fmaxf(mr, __int_as_float(cand[s].x));
            float thr = mr - FIXMARGIN;
            int nq = 0, only = 0;
            for (int s = 0; s < n; s++)
                if (__int_as_float(cand[s].x) >= thr) { nq++; only = cand[s].y; }
            if (nq <= 1) {
                g_ind[row] = only;
                g_slot[row] = atomicAdd(&g_cnti[only], 1);
                out_ind[row] = (float)only;
                resolved = only;
            }
        }
        if (resolved < 0) {
            int w = atomicAdd(&g_nwork, 1);
            g_work[w] = row;
        }
        ind_s[tid] = resolved;
    }
    __syncthreads();

    // fused quantize write for resolved rows: warp w handles rows w*16..+15,
    // coalesced float4 per lane (32 lanes x 16B = one 512B row)
    {
        #pragma unroll
        for (int i = 0; i < 16; i++) {
            int r = warp * 16 + i;
            int ind = ind_s[r];
            if (ind >= 0) {
                float4 e4 = ((const float4*)(embed + (size_t)ind * DIM))[lane];
                ((float4*)(out_q + (size_t)(row0 + r) * DIM))[lane] = e4;
            }
        }
    }
}

// ---------------------------------------------------------------------------
// k_fix2: warp per work-row; lane per candidate, bit-exact R4 chain;
// also writes out_q for its rows (lane-parallel float4)
// ---------------------------------------------------------------------------
__global__ __launch_bounds__(256)
void k_fix2(const float* __restrict__ x, float* __restrict__ out_ind,
            const float* __restrict__ embed, float* __restrict__ out_q) {
    int gw = (blockIdx.x * 256 + threadIdx.x) >> 5;
    int lane = threadIdx.x & 31;
    int nwarps = gridDim.x * 8;
    int nwork = g_nwork;

    for (int i = gw; i < nwork; i += nwarps) {
        int row = g_work[i];
        const float* xr = x + (size_t)row * DIM;
        int n = g_ncand[row];
        float xsq = xsq_row(xr);

        float bd = -3.4e38f;
        int bi = 0x7FFFFFFF;
        if (n <= NCAND) {
            int2 cd = (lane < n) ? g_cand[(size_t)row * NCAND + lane]
                                 : make_int2((int)0xFF800000, 0x7FFFFFFF);
            float raw = __int_as_float(cd.x);
            float mr = raw;
            #pragma unroll
            for (int off = 16; off; off >>= 1)
                mr = fmaxf(mr, __shfl_xor_sync(0xffffffffu, mr, off));
            if (lane < n && raw >= mr - FIXMARGIN) {
                bd = exact_dist(xr, xsq, cd.y);
                bi = cd.y;
            }
        } else {
            for (int c = lane; c < KCB; c += 32) {
                float dist = exact_dist(xr, xsq, c);
                if (dist > bd) { bd = dist; bi = c; }
            }
        }
        #pragma unroll
        for (int off = 16; off; off >>= 1) {
            float ov = __shfl_xor_sync(0xffffffffu, bd, off);
            int   oi = __shfl_xor_sync(0xffffffffu, bi, off);
            if (ov > bd || (ov == bd && oi < bi)) { bd = ov; bi = oi; }
        }
        if (lane == 0) {
            g_ind[row] = bi;
            g_slot[row] = atomicAdd(&g_cnti[bi], 1);
            out_ind[row] = (float)bi;
        }
        // all lanes hold bi after the xor-reduce: coalesced quantize write
        float4 e4 = ((const float4*)(embed + (size_t)bi * DIM))[lane];
        ((float4*)(out_q + (size_t)row * DIM))[lane] = e4;
    }
}

// ---------------------------------------------------------------------------
__global__ void k_scan(const float* __restrict__ cs, float* __restrict__ out_ncs) {
    __shared__ int sh[1024];
    __shared__ float ws[32];
    int tid = threadIdx.x;
    int c = g_cnti[tid];
    sh[tid] = c;
    __syncthreads();
    for (int off = 1; off < 1024; off <<= 1) {
        int t = (tid >= off) ? sh[tid - off] : 0;
        __syncthreads();
        sh[tid] += t;
        __syncthreads();
    }
    g_off[tid] = sh[tid] - c;

    float v = __fadd_rn(__fmul_rn(cs[tid], 0.99f), __fmul_rn(0.01f, (float)c));
    out_ncs[tid] = v;
    float s = v;
    #pragma unroll
    for (int off = 16; off; off >>= 1)
        s += __shfl_xor_sync(0xffffffffu, s, off);
    if ((tid & 31) == 0) ws[tid >> 5] = s;
    __syncthreads();
    if (tid < 32) {
        float t = ws[tid];
        #pragma unroll
        for (int off = 16; off; off >>= 1)
            t += __shfl_xor_sync(0xffffffffu, t, off);
        if (tid == 0) ws[0] = t;
    }
    __syncthreads();
    float total = ws[0];
    g_smoothed[tid] = __fmul_rn(
        __fdiv_rn(__fadd_rn(v, 1e-5f), __fadd_rn(total, 0.01024f)), total);
}

// ---------------------------------------------------------------------------
// k_place: scatter row indices into per-code buckets
// ---------------------------------------------------------------------------
__global__ void k_place() {
    int row = blockIdx.x * 256 + threadIdx.x;
    g_rowlist[g_off[g_ind[row]] + g_slot[row]] = row;
}

__global__ void k_gather(const float* __restrict__ x,
                         const float* __restrict__ ea,
                         float* __restrict__ out_nea,
                         float* __restrict__ out_ne) {
    __shared__ int rs[128];
    int k = blockIdx.x, d = threadIdx.x;
    int cnt = g_cnti[k], off = g_off[k];
    float s = 0.0f;
    for (int base = 0; base < cnt; base += 128) {
        int m = min(128, cnt - base);
        __syncthreads();
        if (d < m) rs[d] = g_rowlist[off + base + d];
        __syncthreads();
        for (int i = 0; i < m; i++)
            s += x[(size_t)rs[i] * DIM + d];
    }
    float r = __fadd_rn(__fmul_rn(ea[k * DIM + d], 0.99f), __fmul_rn(0.01f, s));
    out_nea[k * DIM + d] = r;
    out_ne[k * DIM + d] = __fdiv_rn(r, g_smoothed[k]);
}

// ---------------------------------------------------------------------------
extern "C" void kernel_launch(void* const* d_in, const int* in_sizes, int n_in,
                              void* d_out, int out_size) {
    const float* x     = (const float*)d_in[0];
    const float* embed = (const float*)d_in[1];
    const float* cs    = (const float*)d_in[2];
    const float* ea    = (const float*)d_in[3];

    float* out     = (float*)d_out;
    float* out_q   = out;
    float* out_ind = out + (size_t)N_ROWS * DIM;
    float* out_ncs = out_ind + N_ROWS;
    float* out_nea = out_ncs + KCB;
    float* out_ne  = out_nea + (size_t)KCB * DIM;

    static bool attr_done = false;
    if (!attr_done) {
        cudaFuncSetAttribute(k_main, cudaFuncAttributeMaxDynamicSharedMemorySize,
                             SMEM_BYTES);
        attr_done = true;
    }

    k_pre<<<KCB, DIM>>>(embed);
    k_main<<<N_ROWS / BM, 256, SMEM_BYTES>>>(x, out_ind, embed, out_q);
    k_fix2<<<296, 256>>>(x, out_ind, embed, out_q);
    k_scan<<<1, 1024>>>(cs, out_ncs);
    k_place<<<N_ROWS / 256, 256>>>();
    k_gather<<<KCB, DIM>>>(x, ea, out_nea, out_ne);
}